// round 7
// baseline (speedup 1.0000x reference)
#include <cuda_runtime.h>
#include <math.h>

#define LAYERS 2
#define BB 8
#define TT 512
#define HH 128
#define MM (BB*TT)   // 4096 rows

// ---------------- device scratch ----------------
__device__ float  g_Wt[LAYERS][6][HH*HH];  // transposed weights [l][p][d][h]
__device__ float  g_q[MM*HH];              // q
__device__ float  g_k[MM*HH];              // k / sqrt(H)
__device__ float  g_i[MM*HH];              // exp(i)   (planar, for den warp)
__device__ float  g_f[MM*HH];              // sigm(f)  (planar, for den warp)
__device__ float4 g_gates[MM*HH];          // packed (i, f, v, o) per (m, h)
__device__ float  g_h[MM*HH];              // UNNORMALIZED hidden (o * C.q)
__device__ float  g_rden[MM];              // 1 / max(|n.q|, 1) per (b,t)

// ---------------- weight transpose ----------------
__global__ void transpose_w_kernel(const float* __restrict__ Wq, const float* __restrict__ Wk,
                                   const float* __restrict__ Wv, const float* __restrict__ Wi,
                                   const float* __restrict__ Wf, const float* __restrict__ Wo)
{
    int idx = blockIdx.x * blockDim.x + threadIdx.x;
    const int total = LAYERS * 6 * HH * HH;
    if (idx >= total) return;
    int l   = idx / (6 * HH * HH);
    int rem = idx - l * 6 * HH * HH;
    int p   = rem / (HH * HH);
    int e   = rem - p * (HH * HH);
    int d   = e >> 7;
    int h   = e & 127;
    const float* W = (p == 0) ? Wq : (p == 1) ? Wk : (p == 2) ? Wv
                   : (p == 3) ? Wi : (p == 4) ? Wf : Wo;
    g_Wt[l][p][d * HH + h] = W[l * HH * HH + h * HH + d];
}

// ---------------- projection GEMM + bias + activation ----------------
// 64x64 tile, BK=8, 128 threads, 4x8 microtile. grid (MM/64, 12) = 768 CTAs
// (blockIdx.y: p = y>>1, n-half = y&1). High CTA/SM count hides LDS latency.
// For layer 1 (X==nullptr) the A operand is g_h scaled by g_rden (fused norm).
__global__ __launch_bounds__(128) void proj_gemm_kernel(
    const float* __restrict__ X, int layer,
    const float* __restrict__ bq, const float* __restrict__ bk,
    const float* __restrict__ bv, const float* __restrict__ bi,
    const float* __restrict__ bf, const float* __restrict__ bo)
{
    const float* __restrict__ Xp = X ? X : g_h;
    const int p  = blockIdx.y >> 1;
    const int n0 = (blockIdx.y & 1) << 6;
    const int m0 = blockIdx.x * 64;
    const float* __restrict__ Wt = g_Wt[layer][p];

    __shared__ float As[8][64];
    __shared__ float Bs[8][64];

    const int tid = threadIdx.x;
    const int tx = tid & 7;           // 8 col groups  (x8 = 64)
    const int ty = tid >> 3;          // 16 row groups (x4 = 64)
    const int lm = tid >> 1;          // 0..63 : M row for X load
    const int lk = (tid & 1) << 2;    // 0 or 4
    const int wn = (tid & 15) << 2;   // 0..60
    const int wk = tid >> 4;          // 0..7

    const float rd = X ? 1.0f : g_rden[m0 + lm];  // fused normalization of layer-0 output

    float acc[4][8];
    #pragma unroll
    for (int i = 0; i < 4; i++)
        #pragma unroll
        for (int j = 0; j < 8; j++) acc[i][j] = 0.0f;

    for (int k0 = 0; k0 < HH; k0 += 8) {
        float4 xa = *(const float4*)(Xp + (m0 + lm) * HH + k0 + lk);
        float4 wa = *(const float4*)(Wt + (k0 + wk) * HH + n0 + wn);
        As[lk + 0][lm] = xa.x * rd;
        As[lk + 1][lm] = xa.y * rd;
        As[lk + 2][lm] = xa.z * rd;
        As[lk + 3][lm] = xa.w * rd;
        *(float4*)(&Bs[wk][wn]) = wa;
        __syncthreads();
        #pragma unroll
        for (int kk = 0; kk < 8; kk++) {
            float a[4], b[8];
            *(float4*)(a)     = *(const float4*)(&As[kk][ty * 4]);
            *(float4*)(b)     = *(const float4*)(&Bs[kk][tx * 8]);
            *(float4*)(b + 4) = *(const float4*)(&Bs[kk][tx * 8 + 4]);
            #pragma unroll
            for (int i = 0; i < 4; i++)
                #pragma unroll
                for (int j = 0; j < 8; j++)
                    acc[i][j] = fmaf(a[i], b[j], acc[i][j]);
        }
        __syncthreads();
    }

    const float* __restrict__ bias =
        (p == 0) ? bq : (p == 1) ? bk : (p == 2) ? bv
      : (p == 3) ? bi : (p == 4) ? bf : bo;
    const float kscale = 0.088388347648318447f;  // 1/sqrt(128)

    #pragma unroll
    for (int i = 0; i < 4; i++) {
        const int m = m0 + ty * 4 + i;
        #pragma unroll
        for (int j = 0; j < 8; j++) {
            const int h = n0 + tx * 8 + j;
            float v = acc[i][j] + bias[layer * HH + h];
            const int e = m * HH + h;
            if (p == 0) {
                g_q[e] = v;
            } else if (p == 1) {
                g_k[e] = v * kscale;
            } else if (p == 2) {
                g_gates[e].z = v;                       // v
            } else if (p == 3) {
                v = expf(v);
                g_i[e] = v; g_gates[e].x = v;           // i
            } else if (p == 4) {
                v = 1.0f / (1.0f + expf(-v));
                g_f[e] = v; g_gates[e].y = v;           // f
            } else {
                v = 1.0f / (1.0f + expf(-v));
                g_gates[e].w = v;                       // o
            }
        }
    }
}

// ---------------- barrier-free mLSTM scan, 2 adjacent rows per warp ----------------
// grid (33, 8), block 64 (2 warps). NO smem, NO __syncthreads.
//  bx < 32 : warp (bx*2 + w) owns rows r0 = 2*wb, r1 = r0+1 of batch b.
//            Lane owns C[r0][c4..c4+3] and C[r1][c4..c4+3]. q4/k4 loaded once
//            per step and reused for both rows (halves global-load traffic);
//            the two gate float4s are 16B apart -> same cache line.
//            h_tilde partials batch-reduced 4 steps x 2 rows at a time.
//            Output written UNNORMALIZED (o * C.q).
//  bx == 32: warp 0 computes the denominator recurrence n_t = f*n + i*k and
//            stores rden[b][t] = 1/max(|n_{t-1}.q_t|, 1).
__global__ __launch_bounds__(64) void scan_kernel()
{
    const int b    = blockIdx.y;
    const int w    = threadIdx.x >> 5;
    const int lane = threadIdx.x & 31;
    const int c4   = lane << 2;

    if (blockIdx.x == 32) {
        // ---- denominator warp ----
        if (w != 0) return;
        const float* __restrict__ Pq = g_q + b * TT * HH + c4;
        const float* __restrict__ Pk = g_k + b * TT * HH + c4;
        const float* __restrict__ Pi = g_i + b * TT * HH + c4;
        const float* __restrict__ Pf = g_f + b * TT * HH + c4;
        float* __restrict__ Dr = g_rden + b * TT;

        float4 qb[8], kb[8], ib[8], fb[8];
        #pragma unroll
        for (int s = 0; s < 8; s++) {
            qb[s] = *(const float4*)(Pq + s * HH);
            kb[s] = *(const float4*)(Pk + s * HH);
            ib[s] = *(const float4*)(Pi + s * HH);
            fb[s] = *(const float4*)(Pf + s * HH);
        }
        float n0 = 0.f, n1 = 0.f, n2 = 0.f, n3 = 0.f;

        for (int gI = 0; gI < 64; gI++) {
            float pd[8];
            #pragma unroll
            for (int s = 0; s < 8; s++) {
                float4 q = qb[s], k = kb[s], ii = ib[s], ff = fb[s];
                pd[s] = n0 * q.x + n1 * q.y + n2 * q.z + n3 * q.w;  // uses OLD n
                n0 = fmaf(ff.x, n0, ii.x * k.x);
                n1 = fmaf(ff.y, n1, ii.y * k.y);
                n2 = fmaf(ff.z, n2, ii.z * k.z);
                n3 = fmaf(ff.w, n3, ii.w * k.w);
                if (gI < 63) {
                    const int off = (gI * 8 + s + 8) * HH;
                    qb[s] = *(const float4*)(Pq + off);
                    kb[s] = *(const float4*)(Pk + off);
                    ib[s] = *(const float4*)(Pi + off);
                    fb[s] = *(const float4*)(Pf + off);
                }
            }
            #pragma unroll
            for (int o = 16; o > 0; o >>= 1)
                #pragma unroll
                for (int s = 0; s < 8; s++)
                    pd[s] += __shfl_xor_sync(0xffffffffu, pd[s], o);
            if (lane == 0) {
                #pragma unroll
                for (int s = 0; s < 8; s++)
                    Dr[gI * 8 + s] = 1.0f / fmaxf(fabsf(pd[s]), 1.0f);
            }
        }
        return;
    }

    // ---- row warps: 2 adjacent rows per warp ----
    const int wb = blockIdx.x * 2 + w;   // 0..63
    const int r0 = wb * 2;
    const int r1 = r0 + 1;
    const float*  __restrict__ Pq = g_q + b * TT * HH + c4;
    const float*  __restrict__ Pk = g_k + b * TT * HH + c4;
    const float4* __restrict__ Pg = g_gates + b * TT * HH;
    float* __restrict__ Dst = g_h + b * TT * HH;

    float4 qb[4], kb[4], g0[4], g1[4];
    #pragma unroll
    for (int s = 0; s < 4; s++) {
        qb[s] = *(const float4*)(Pq + s * HH);
        kb[s] = *(const float4*)(Pk + s * HH);
        g0[s] = Pg[s * HH + r0];
        g1[s] = Pg[s * HH + r1];
    }
    float A0 = 0.f, A1 = 0.f, A2 = 0.f, A3 = 0.f;   // C row r0
    float B0 = 0.f, B1 = 0.f, B2 = 0.f, B3 = 0.f;   // C row r1

    for (int gI = 0; gI < 128; gI++) {
        float dp0[4], dp1[4];
        #pragma unroll
        for (int s = 0; s < 4; s++) {
            float4 q = qb[s], k = kb[s];
            float4 ga = g0[s], gc = g1[s];    // (i, f, v, o) for r0, r1
            dp0[s] = ga.w * (A0 * q.x + A1 * q.y + A2 * q.z + A3 * q.w);
            dp1[s] = gc.w * (B0 * q.x + B1 * q.y + B2 * q.z + B3 * q.w);
            const float aa = ga.x * ga.z;
            A0 = fmaf(ga.y, A0, aa * k.x);
            A1 = fmaf(ga.y, A1, aa * k.y);
            A2 = fmaf(ga.y, A2, aa * k.z);
            A3 = fmaf(ga.y, A3, aa * k.w);
            const float bb = gc.x * gc.z;
            B0 = fmaf(gc.y, B0, bb * k.x);
            B1 = fmaf(gc.y, B1, bb * k.y);
            B2 = fmaf(gc.y, B2, bb * k.z);
            B3 = fmaf(gc.y, B3, bb * k.w);
            if (gI < 127) {
                const int off = (gI * 4 + s + 4) * HH;
                qb[s] = *(const float4*)(Pq + off);
                kb[s] = *(const float4*)(Pk + off);
                g0[s] = Pg[off + r0];
                g1[s] = Pg[off + r1];
            }
        }
        // 8 independent butterfly reductions (pipelined, level-synchronous)
        #pragma unroll
        for (int o = 16; o > 0; o >>= 1) {
            #pragma unroll
            for (int s = 0; s < 4; s++) {
                dp0[s] += __shfl_xor_sync(0xffffffffu, dp0[s], o);
                dp1[s] += __shfl_xor_sync(0xffffffffu, dp1[s], o);
            }
        }
        if (lane == 0) {
            #pragma unroll
            for (int s = 0; s < 4; s++) {
                const int t = gI * 4 + s;
                Dst[t * HH + r0] = dp0[s];        // unnormalized
                Dst[t * HH + r1] = dp1[s];
            }
        }
    }
}

// ---------------- final normalization ----------------
__global__ void normalize_kernel(float* __restrict__ out)
{
    const int idx = blockIdx.x * 256 + threadIdx.x;
    out[idx] = g_h[idx] * g_rden[idx >> 7];
}

// ---------------- launcher ----------------
extern "C" void kernel_launch(void* const* d_in, const int* in_sizes, int n_in,
                              void* d_out, int out_size)
{
    const float* x  = (const float*)d_in[0];
    const float* Wq = (const float*)d_in[1];
    const float* Wk = (const float*)d_in[2];
    const float* Wv = (const float*)d_in[3];
    const float* Wi = (const float*)d_in[4];
    const float* Wf = (const float*)d_in[5];
    const float* Wo = (const float*)d_in[6];
    const float* bq = (const float*)d_in[7];
    const float* bk = (const float*)d_in[8];
    const float* bv = (const float*)d_in[9];
    const float* bi = (const float*)d_in[10];
    const float* bf = (const float*)d_in[11];
    const float* bo = (const float*)d_in[12];
    float* out = (float*)d_out;

    const int total_w = LAYERS * 6 * HH * HH;
    transpose_w_kernel<<<(total_w + 255) / 256, 256>>>(Wq, Wk, Wv, Wi, Wf, Wo);

    dim3 ggrid(MM / 64, 12);
    dim3 sgrid(33, BB);

    // layer 0
    proj_gemm_kernel<<<ggrid, 128>>>(x, 0, bq, bk, bv, bi, bf, bo);
    scan_kernel<<<sgrid, 64>>>();                         // g_h (raw) + g_rden
    // layer 1 (normalization of layer-0 output fused into A-load)
    proj_gemm_kernel<<<ggrid, 128>>>(nullptr, 1, bq, bk, bv, bi, bf, bo);
    scan_kernel<<<sgrid, 64>>>();                         // g_h (raw) + g_rden
    // final normalize into d_out
    normalize_kernel<<<(MM * HH) / 256, 256>>>(out);
}